// round 11
// baseline (speedup 1.0000x reference)
#include <cuda_runtime.h>
#include <cuda_bf16.h>
#include <cstdint>

// ---------------------------------------------------------------------------
// Problem constants
// ---------------------------------------------------------------------------
#define NROWS 2048
#define NFEAT 128
#define TILE  128
#define GRID  256                 // 16x16 tiles, one CTA each; 2/SM resident
#define NTHREADS 512

// ---------------------------------------------------------------------------
// Device scratch (zero-initialized; no allocation allowed)
// ---------------------------------------------------------------------------
__device__ float g_norm[NROWS];         // row norms of quantized X (by diag CTAs)
__device__ float g_sd[16][NFEAT];       // per-diagonal-block feature sums
__device__ float g_snd[16];             // per-diagonal-block norm sums
__device__ float g_c;                   // inv2s * log2(e)
__device__ int   g_gctr;                // diagonal-stats arrive counter (16)
__device__ int   g_ctr2;                // exit counter (for reset)
__device__ int   g_flag2;               // sigma ready

// ---------------------------------------------------------------------------
// Helpers
// ---------------------------------------------------------------------------
__device__ __forceinline__ uint32_t smem_to_u32(const void* p) {
    uint32_t a;
    asm("{ .reg .u64 t; cvta.to.shared.u64 t, %1; cvt.u32.u64 %0, t; }" : "=r"(a) : "l"(p));
    return a;
}

__device__ __forceinline__ void ldmatrix_x4(uint32_t& r0, uint32_t& r1,
                                            uint32_t& r2, uint32_t& r3, uint32_t addr) {
    asm volatile("ldmatrix.sync.aligned.m8n8.x4.shared.b16 {%0,%1,%2,%3}, [%4];"
                 : "=r"(r0), "=r"(r1), "=r"(r2), "=r"(r3) : "r"(addr));
}

__device__ __forceinline__ void mma_16816(float* d, const uint32_t* a, const uint32_t* b) {
    asm volatile(
        "mma.sync.aligned.m16n8k16.row.col.f32.bf16.bf16.f32 "
        "{%0,%1,%2,%3}, {%4,%5,%6,%7}, {%8,%9}, {%0,%1,%2,%3};"
        : "+f"(d[0]), "+f"(d[1]), "+f"(d[2]), "+f"(d[3])
        : "r"(a[0]), "r"(a[1]), "r"(a[2]), "r"(a[3]), "r"(b[0]), "r"(b[1]));
}

__device__ __forceinline__ float ex2f(float x) {
    float r;
    asm("ex2.approx.ftz.f32 %0, %1;" : "=f"(r) : "f"(x));
    return r;
}

// bf16x2 pack: lo = x, hi = y
__device__ __forceinline__ uint32_t bf2(float x, float y) {
    uint32_t r;
    asm("cvt.rn.bf16x2.f32 %0, %1, %2;" : "=r"(r) : "f"(y), "f"(x));
    return r;
}

__device__ __forceinline__ void spin_until(volatile int* fp) {
    while (*fp == 0) { __nanosleep(32); }
}

// ---------------------------------------------------------------------------
// Smem layout: ci/cj const tiles + A,B bf16 tiles (128 x 256B each) +
// stats scratch (16 warps x 128 floats) used only by diagonal CTAs.
// ---------------------------------------------------------------------------
#define OFF_CI  0
#define OFF_CJ  512
#define OFF_A   1024
#define OFF_B   (1024 + 32768)
#define OFF_FS  (OFF_B + 32768)
#define SMEM_TOTAL (OFF_FS + 16 * NFEAT * 4 + 64)   // 74816 B -> 2 CTAs/SM

// ---------------------------------------------------------------------------
// ONE fused kernel. No pre-pass: diagonal CTAs (bi==bj) compute norms +
// feature sums FROM THEIR SMEM TILE; the 16th to finish reduces sigma.
// flag2 (sigma) gates only the epilogue.
// ---------------------------------------------------------------------------
__global__ void __launch_bounds__(NTHREADS, 2) gauss_fused_kernel(
        const float* __restrict__ X, float* __restrict__ out) {
    extern __shared__ char smem[];
    uint32_t sb = smem_to_u32(smem);
    int b   = blockIdx.x;
    int tid = threadIdx.x;
    int wid = tid >> 5;
    int lid = tid & 31;
    int bj  = b & 15;
    int bi  = b >> 4;

    __shared__ float sn[16];
    __shared__ float red[4];
    __shared__ int   s_final;

    // =============== Tile load: inline f32->bf16 quantization ===============
    const float4* Af = reinterpret_cast<const float4*>(X + (size_t)bi * TILE * NFEAT);
    const float4* Bf = reinterpret_cast<const float4*>(X + (size_t)bj * TILE * NFEAT);
    #pragma unroll
    for (int g = tid; g < 2048; g += NTHREADS) {       // 128 rows x 16 chunks
        int row = g >> 4, ch = g & 15;
        uint32_t off = (uint32_t)row * 256u + (uint32_t)(ch ^ (row & 7)) * 16u;
        float4 a0 = Af[row * 32 + ch * 2];
        float4 a1 = Af[row * 32 + ch * 2 + 1];
        uint4 oa;
        oa.x = bf2(a0.x, a0.y); oa.y = bf2(a0.z, a0.w);
        oa.z = bf2(a1.x, a1.y); oa.w = bf2(a1.z, a1.w);
        *reinterpret_cast<uint4*>(smem + OFF_A + off) = oa;
        float4 b0 = Bf[row * 32 + ch * 2];
        float4 b1 = Bf[row * 32 + ch * 2 + 1];
        uint4 ob;
        ob.x = bf2(b0.x, b0.y); ob.y = bf2(b0.z, b0.w);
        ob.z = bf2(b1.x, b1.y); ob.w = bf2(b1.z, b1.w);
        *reinterpret_cast<uint4*>(smem + OFF_B + off) = ob;
    }
    __syncthreads();

    // =============== Diagonal CTAs: stats from the smem A tile =============
    if (bi == bj) {
        // lane l covers features l*4..l*4+3 (logical byte l*8 of each row)
        float fs0 = 0.f, fs1 = 0.f, fs2 = 0.f, fs3 = 0.f;
        float wnorm = 0.f;
        #pragma unroll
        for (int r8 = 0; r8 < 8; r8++) {
            int r = wid * 8 + r8;
            uint32_t addr = sb + OFF_A + (uint32_t)r * 256u
                          + ((uint32_t)((lid >> 1) ^ (r & 7)) << 4) + ((uint32_t)(lid & 1) << 3);
            uint32_t v0, v1;
            asm volatile("ld.shared.v2.u32 {%0,%1}, [%2];" : "=r"(v0), "=r"(v1) : "r"(addr));
            float2 p0 = __bfloat1622float2(*reinterpret_cast<__nv_bfloat162*>(&v0));
            float2 p1 = __bfloat1622float2(*reinterpret_cast<__nv_bfloat162*>(&v1));
            fs0 += p0.x; fs1 += p0.y; fs2 += p1.x; fs3 += p1.y;
            float sq = p0.x * p0.x + p0.y * p0.y + p1.x * p1.x + p1.y * p1.y;
            #pragma unroll
            for (int o = 16; o > 0; o >>= 1) sq += __shfl_xor_sync(0xFFFFFFFFu, sq, o);
            if (lid == 0) { g_norm[bi * TILE + r] = sq; wnorm += sq; }
        }
        float* ss = reinterpret_cast<float*>(smem + OFF_FS);   // [16][128]
        ss[wid * NFEAT + lid * 4 + 0] = fs0;
        ss[wid * NFEAT + lid * 4 + 1] = fs1;
        ss[wid * NFEAT + lid * 4 + 2] = fs2;
        ss[wid * NFEAT + lid * 4 + 3] = fs3;
        if (lid == 0) sn[wid] = wnorm;
        __syncthreads();
        if (tid < NFEAT) {
            float t = 0.f;
            #pragma unroll
            for (int w = 0; w < 16; w++) t += ss[w * NFEAT + tid];
            g_sd[bi][tid] = t;
        }
        if (tid == 0) {
            float t = 0.f;
            #pragma unroll
            for (int w = 0; w < 16; w++) t += sn[w];
            g_snd[bi] = t;
        }
        __threadfence();
        __syncthreads();
        if (tid == 0) s_final = (atomicAdd(&g_gctr, 1) == 15) ? 1 : 0;
        __syncthreads();

        // 16th diagonal CTA: final sigma reduce
        if (s_final) {
            if (tid < NFEAT) {
                float s = 0.f;
                #pragma unroll
                for (int q = 0; q < 16; q++) s += __ldcg(&g_sd[q][tid]);
                float v = s * s;
                #pragma unroll
                for (int o = 16; o > 0; o >>= 1) v += __shfl_xor_sync(0xFFFFFFFFu, v, o);
                if (lid == 0) red[wid] = v;
            }
            __syncthreads();
            if (tid == 0) {
                float S2 = red[0] + red[1] + red[2] + red[3];
                float sumn = 0.f;
                #pragma unroll
                for (int q = 0; q < 16; q++) sumn += __ldcg(&g_snd[q]);
                float Nf = (float)NROWS;
                float inv2s = (Nf * Nf) / (4.f * Nf * sumn - 4.f * S2);
                g_c = inv2s * 1.4426950408889634f;   // fold log2(e) for ex2
                __threadfence();
                *((volatile int*)&g_flag2) = 1;
            }
        }
    }

    // =============== per-warp MMA: 4x4 grid of 32x32 subtiles ==============
    int wm  = (wid & 3) * 32;
    int wn2 = (wid >> 2) * 32;

    float d[2][4][4];
    #pragma unroll
    for (int mt = 0; mt < 2; mt++)
        #pragma unroll
        for (int nt = 0; nt < 4; nt++)
            #pragma unroll
            for (int e = 0; e < 4; e++) d[mt][nt][e] = 0.f;

    uint32_t a_row  = (uint32_t)(wm + (lid & 15));
    uint32_t a_cbit = (uint32_t)(lid >> 4);
    uint32_t a_rl   = a_row & 7;
    uint32_t a_base0 = sb + OFF_A + a_row * 256u;
    uint32_t a_base1 = a_base0 + 16u * 256u;

    uint32_t b_row  = (uint32_t)(wn2 + (lid & 7) + ((lid & 16) >> 1));
    uint32_t b_cbit = (uint32_t)((lid >> 3) & 1);
    uint32_t b_rl   = b_row & 7;
    uint32_t b_base0 = sb + OFF_B + b_row * 256u;
    uint32_t b_base1 = b_base0 + 16u * 256u;

    #pragma unroll
    for (int kc = 0; kc < 8; kc++) {
        uint32_t af[2][4];
        uint32_t bfr[4][2];
        uint32_t sca = ((uint32_t)(2 * kc) + a_cbit) ^ a_rl;
        ldmatrix_x4(af[0][0], af[0][1], af[0][2], af[0][3], a_base0 + (sca << 4));
        ldmatrix_x4(af[1][0], af[1][1], af[1][2], af[1][3], a_base1 + (sca << 4));
        uint32_t scb = ((uint32_t)(2 * kc) + b_cbit) ^ b_rl;
        ldmatrix_x4(bfr[0][0], bfr[0][1], bfr[1][0], bfr[1][1], b_base0 + (scb << 4));
        ldmatrix_x4(bfr[2][0], bfr[2][1], bfr[3][0], bfr[3][1], b_base1 + (scb << 4));
        #pragma unroll
        for (int mt = 0; mt < 2; mt++)
            #pragma unroll
            for (int nt = 0; nt < 4; nt++)
                mma_16816(d[mt][nt], af[mt], bfr[nt]);
    }

    // =============== Wait for sigma (long done by now) ====================
    if (tid == 0) spin_until(&g_flag2);
    __syncthreads();
    float c = __ldcg(&g_c);

    // const tiles from g_norm (written by diagonal CTAs; ordered by flag2)
    if (tid < TILE)
        reinterpret_cast<float*>(smem + OFF_CI)[tid] =
            -__ldcg(&g_norm[bi * TILE + tid]) * c;
    else if (tid < 2 * TILE)
        reinterpret_cast<float*>(smem + OFF_CJ)[tid - TILE] =
            -__ldcg(&g_norm[bj * TILE + (tid - TILE)]) * c;
    __syncthreads();

    // epilogue: out = ex2(dot * 2c + ci + cj)
    float sc2 = 2.f * c;
    const float* cis = reinterpret_cast<const float*>(smem + OFF_CI);
    const float* cjs = reinterpret_cast<const float*>(smem + OFF_CJ);
    int quad = lid >> 2;
    int qt   = lid & 3;

    #pragma unroll
    for (int mt = 0; mt < 2; mt++) {
        #pragma unroll
        for (int half = 0; half < 2; half++) {
            int r  = wm + mt * 16 + quad + half * 8;
            float ci = cis[r];
            float* orow = out + (size_t)(bi * TILE + r) * NROWS + (size_t)bj * TILE + wn2;
            #pragma unroll
            for (int nt = 0; nt < 4; nt++) {
                int col = nt * 8 + qt * 2;
                float e0 = fmaf(d[mt][nt][half * 2 + 0], sc2, ci + cjs[wn2 + col]);
                float e1 = fmaf(d[mt][nt][half * 2 + 1], sc2, ci + cjs[wn2 + col + 1]);
                *reinterpret_cast<float2*>(orow + col) = make_float2(ex2f(e0), ex2f(e1));
            }
        }
    }

    // =============== reset counters for next graph replay ===============
    __syncthreads();
    if (tid == 0) {
        if (atomicAdd(&g_ctr2, 1) == GRID - 1) {   // last CTA to exit
            g_gctr  = 0;
            g_ctr2  = 0;
            g_flag2 = 0;
        }
    }
}

// ---------------------------------------------------------------------------
// Launch
// ---------------------------------------------------------------------------
extern "C" void kernel_launch(void* const* d_in, const int* in_sizes, int n_in,
                              void* d_out, int out_size) {
    const float* X = (const float*)d_in[0];
    float* out = (float*)d_out;
    (void)in_sizes; (void)n_in; (void)out_size;

    cudaFuncSetAttribute(gauss_fused_kernel,
                         cudaFuncAttributeMaxDynamicSharedMemorySize, SMEM_TOTAL);

    gauss_fused_kernel<<<GRID, NTHREADS, SMEM_TOTAL>>>(X, out);
}

// round 12
// speedup vs baseline: 1.0795x; 1.0795x over previous
#include <cuda_runtime.h>
#include <cuda_bf16.h>
#include <cstdint>

// ---------------------------------------------------------------------------
// Problem constants
// ---------------------------------------------------------------------------
#define NROWS 2048
#define NFEAT 128
#define TILE  128
#define GRID  256                 // 16x16 tiles, one CTA each; 2/SM resident
#define NTHREADS 512

// ---------------------------------------------------------------------------
// Device scratch (zero-initialized; no allocation allowed)
// ---------------------------------------------------------------------------
__device__ __nv_bfloat16 g_Xb[NROWS * NFEAT];   // bf16-quantized X (phase 1)
__device__ float g_norm[NROWS];                 // row norms of quantized X
__device__ float g_s_part[GRID][NFEAT];         // per-CTA feature-sum partials
__device__ float g_sumn_part[GRID];             // per-CTA sum-of-norms partials
__device__ float g_s2[8][NFEAT];                // level-2 feature-sum partials
__device__ float g_sn2[8];                      // level-2 sum-of-norms partials
__device__ float g_c;                           // inv2s * log2(e)
__device__ int   g_ctr;                         // global phase-1 counter
__device__ int   g_gc[16];                      // per-group phase-1 counters
__device__ int   g_gflag[16];                   // per-group rows-ready flags
__device__ int   g_ctr3;                        // sigma level-2 counter
__device__ int   g_ctr2;                        // exit counter
__device__ int   g_flag1;                       // ALL phase-1 partials visible
__device__ int   g_flag2;                       // sigma ready

// ---------------------------------------------------------------------------
// Helpers
// ---------------------------------------------------------------------------
__device__ __forceinline__ uint32_t smem_to_u32(const void* p) {
    uint32_t a;
    asm("{ .reg .u64 t; cvta.to.shared.u64 t, %1; cvt.u32.u64 %0, t; }" : "=r"(a) : "l"(p));
    return a;
}

__device__ __forceinline__ void ldmatrix_x4(uint32_t& r0, uint32_t& r1,
                                            uint32_t& r2, uint32_t& r3, uint32_t addr) {
    asm volatile("ldmatrix.sync.aligned.m8n8.x4.shared.b16 {%0,%1,%2,%3}, [%4];"
                 : "=r"(r0), "=r"(r1), "=r"(r2), "=r"(r3) : "r"(addr));
}

__device__ __forceinline__ void mma_16816(float* d, const uint32_t* a, const uint32_t* b) {
    asm volatile(
        "mma.sync.aligned.m16n8k16.row.col.f32.bf16.bf16.f32 "
        "{%0,%1,%2,%3}, {%4,%5,%6,%7}, {%8,%9}, {%0,%1,%2,%3};"
        : "+f"(d[0]), "+f"(d[1]), "+f"(d[2]), "+f"(d[3])
        : "r"(a[0]), "r"(a[1]), "r"(a[2]), "r"(a[3]), "r"(b[0]), "r"(b[1]));
}

__device__ __forceinline__ float ex2f(float x) {
    float r;
    asm("ex2.approx.ftz.f32 %0, %1;" : "=f"(r) : "f"(x));
    return r;
}

__device__ __forceinline__ void spin_until(volatile int* fp) {
    while (*fp == 0) { __nanosleep(32); }
}

// cp.async 16B, L2-coherent (.cg): GMEM -> SMEM, no intermediate registers
#define CP16(dst_smem, src_gmem)                                                \
    asm volatile("cp.async.cg.shared.global [%0], [%1], 16;"                    \
                 :: "r"(dst_smem), "l"(src_gmem) : "memory")
#define CP_COMMIT()   asm volatile("cp.async.commit_group;" ::: "memory")
#define CP_WAIT(n)    asm volatile("cp.async.wait_group %0;" :: "n"(n) : "memory")

// ---------------------------------------------------------------------------
// Smem layout: ci/cj const tiles + A,B bf16 tiles (128 x 256B each) + sigma
// scratch. OFF_A reused for phase-1 partials (before tile copies start).
// ---------------------------------------------------------------------------
#define OFF_CI  0
#define OFF_CJ  512
#define OFF_A   1024
#define OFF_B   (1024 + 32768)
#define OFF_FS  (OFF_B + 32768)
#define SMEM_TOTAL (OFF_FS + 2048)      // 68608 B -> 2 CTAs/SM

// one K-step of the MMA loop
__device__ __forceinline__ void k_step(
        int kc, float d[2][4][4],
        uint32_t a_base0, uint32_t a_base1, uint32_t a_cbit, uint32_t a_rl,
        uint32_t b_base0, uint32_t b_base1, uint32_t b_cbit, uint32_t b_rl) {
    uint32_t af[2][4];
    uint32_t bfr[4][2];
    uint32_t sca = ((uint32_t)(2 * kc) + a_cbit) ^ a_rl;
    ldmatrix_x4(af[0][0], af[0][1], af[0][2], af[0][3], a_base0 + (sca << 4));
    ldmatrix_x4(af[1][0], af[1][1], af[1][2], af[1][3], a_base1 + (sca << 4));
    uint32_t scb = ((uint32_t)(2 * kc) + b_cbit) ^ b_rl;
    ldmatrix_x4(bfr[0][0], bfr[0][1], bfr[1][0], bfr[1][1], b_base0 + (scb << 4));
    ldmatrix_x4(bfr[2][0], bfr[2][1], bfr[3][0], bfr[3][1], b_base1 + (scb << 4));
    #pragma unroll
    for (int mt = 0; mt < 2; mt++)
        #pragma unroll
        for (int nt = 0; nt < 4; nt++)
            mma_16816(d[mt][nt], af[mt], bfr[nt]);
}

// ---------------------------------------------------------------------------
// ONE fused kernel:
//   phase 1 -> group flags -> cp.async pipelined tiles -> MMA (overlapped)
//   sigma on CTAs 0..7 (overlapped with their own cp.asyncs + others' GEMM)
//   flag2 gates only the epilogue.
// ---------------------------------------------------------------------------
__global__ void __launch_bounds__(NTHREADS, 2) gauss_fused_kernel(
        const float* __restrict__ X, float* __restrict__ out) {
    extern __shared__ char smem[];
    uint32_t sb = smem_to_u32(smem);
    int b   = blockIdx.x;
    int tid = threadIdx.x;
    int wid = tid >> 5;
    int lid = tid & 31;
    int bj  = b & 15;
    int bi  = b >> 4;

    __shared__ float sn[8];
    __shared__ float red[5];
    __shared__ int   s_last3;

    // =============== Phase 1: quantize 8 rows (group = bi), partials =======
    {
        float* ss = reinterpret_cast<float*>(smem + OFF_A);   // [8][128]
        if (wid < 8) {
            int row = b * 8 + wid;                            // row group == bi
            float4 v = reinterpret_cast<const float4*>(X + (size_t)row * NFEAT)[lid];
            __nv_bfloat16 b0 = __float2bfloat16(v.x);
            __nv_bfloat16 b1 = __float2bfloat16(v.y);
            __nv_bfloat16 b2 = __float2bfloat16(v.z);
            __nv_bfloat16 b3 = __float2bfloat16(v.w);
            __nv_bfloat162* dst =
                reinterpret_cast<__nv_bfloat162*>(g_Xb + (size_t)row * NFEAT) + lid * 2;
            dst[0] = __nv_bfloat162(b0, b1);
            dst[1] = __nv_bfloat162(b2, b3);
            float fx = __bfloat162float(b0), fy = __bfloat162float(b1);
            float fz = __bfloat162float(b2), fw = __bfloat162float(b3);
            float sq = fx * fx + fy * fy + fz * fz + fw * fw;
            #pragma unroll
            for (int o = 16; o > 0; o >>= 1) sq += __shfl_xor_sync(0xFFFFFFFFu, sq, o);
            if (lid == 0) { g_norm[row] = sq; sn[wid] = sq; }
            ss[wid * NFEAT + lid * 4 + 0] = fx;
            ss[wid * NFEAT + lid * 4 + 1] = fy;
            ss[wid * NFEAT + lid * 4 + 2] = fz;
            ss[wid * NFEAT + lid * 4 + 3] = fw;
        }
        __syncthreads();
        if (tid < NFEAT) {
            float t = 0.f;
            #pragma unroll
            for (int w = 0; w < 8; w++) t += ss[w * NFEAT + tid];
            g_s_part[b][tid] = t;
        }
        if (tid == 0) {
            float t = 0.f;
            #pragma unroll
            for (int w = 0; w < 8; w++) t += sn[w];
            g_sumn_part[b] = t;
        }
    }

    __threadfence();
    __syncthreads();
    if (tid == 0) {
        if (atomicAdd(&g_ctr, 1) == GRID - 1)
            *((volatile int*)&g_flag1) = 1;           // all partials visible
        if (atomicAdd(&g_gc[bi], 1) == 15)
            *((volatile int*)&g_gflag[bi]) = 1;       // this row-group ready
    }
    __syncthreads();

    // =============== Wait only for the two row-groups we consume ===========
    if (tid == 0)  spin_until((volatile int*)&g_gflag[bi]);
    if (tid == 32) spin_until((volatile int*)&g_gflag[bj]);
    __syncthreads();

    // =============== cp.async pipelined tile copies (two K-halves) =========
    const char* Ag = reinterpret_cast<const char*>(g_Xb) + (size_t)bi * TILE * 256;
    const char* Bg = reinterpret_cast<const char*>(g_Xb) + (size_t)bj * TILE * 256;
    #pragma unroll
    for (int h = 0; h < 2; h++) {
        #pragma unroll
        for (int t = 0; t < 2; t++) {
            int q   = tid + t * NTHREADS;     // 0..1023
            int row = q >> 3;
            int ch  = h * 8 + (q & 7);
            uint32_t soff = (uint32_t)row * 256u + ((uint32_t)(ch ^ (row & 7)) << 4);
            uint32_t goff = (uint32_t)row * 256u + (uint32_t)ch * 16u;
            CP16(sb + OFF_A + soff, Ag + goff);
            CP16(sb + OFF_B + soff, Bg + goff);
        }
        CP_COMMIT();
    }

    // =============== Sigma on CTAs 0..7 (overlaps own cp.asyncs) ===========
    if (b < 8) {
        if (tid == 0) spin_until((volatile int*)&g_flag1);
        __syncthreads();
        float* ss2 = reinterpret_cast<float*>(smem + OFF_FS);  // [4][128]
        {
            int f = tid & 127;
            int g = tid >> 7;
            float sf = 0.f;
            #pragma unroll
            for (int p = b * 32 + g * 8; p < b * 32 + g * 8 + 8; p++)
                sf += __ldcg(&g_s_part[p][f]);
            ss2[g * NFEAT + f] = sf;
        }
        if (tid < 32) {
            float sna = __ldcg(&g_sumn_part[b * 32 + tid]);
            #pragma unroll
            for (int o = 16; o > 0; o >>= 1) sna += __shfl_xor_sync(0xFFFFFFFFu, sna, o);
            if (tid == 0) g_sn2[b] = sna;
        }
        __syncthreads();
        if (tid < NFEAT) {
            g_s2[b][tid] = ss2[tid] + ss2[NFEAT + tid] +
                           ss2[2 * NFEAT + tid] + ss2[3 * NFEAT + tid];
        }
        __threadfence();
        __syncthreads();
        if (tid == 0) s_last3 = (atomicAdd(&g_ctr3, 1) == 7) ? 1 : 0;
        __syncthreads();
        if (s_last3) {
            if (tid < NFEAT) {
                float s = 0.f;
                #pragma unroll
                for (int q = 0; q < 8; q++) s += __ldcg(&g_s2[q][tid]);
                float v = s * s;
                #pragma unroll
                for (int o = 16; o > 0; o >>= 1) v += __shfl_xor_sync(0xFFFFFFFFu, v, o);
                if (lid == 0) red[wid] = v;
            }
            if (tid >= 480) {
                float sna = (lid < 8) ? __ldcg(&g_sn2[lid]) : 0.f;
                #pragma unroll
                for (int o = 4; o > 0; o >>= 1) sna += __shfl_xor_sync(0xFFFFFFFFu, sna, o);
                if (lid == 0) red[4] = sna;
            }
            __syncthreads();
            if (tid == 0) {
                float S2   = red[0] + red[1] + red[2] + red[3];
                float sumn = red[4];
                float Nf = (float)NROWS;
                float inv2s = (Nf * Nf) / (4.f * Nf * sumn - 4.f * S2);
                g_c = inv2s * 1.4426950408889634f;   // fold log2(e) for ex2
                __threadfence();
                *((volatile int*)&g_flag2) = 1;
            }
        }
    }

    // =============== MMA: 4x4 warp grid, pipelined over the two halves =====
    int wm  = (wid & 3) * 32;
    int wn2 = (wid >> 2) * 32;

    float d[2][4][4];
    #pragma unroll
    for (int mt = 0; mt < 2; mt++)
        #pragma unroll
        for (int nt = 0; nt < 4; nt++)
            #pragma unroll
            for (int e = 0; e < 4; e++) d[mt][nt][e] = 0.f;

    uint32_t a_row  = (uint32_t)(wm + (lid & 15));
    uint32_t a_cbit = (uint32_t)(lid >> 4);
    uint32_t a_rl   = a_row & 7;
    uint32_t a_base0 = sb + OFF_A + a_row * 256u;
    uint32_t a_base1 = a_base0 + 16u * 256u;

    uint32_t b_row  = (uint32_t)(wn2 + (lid & 7) + ((lid & 16) >> 1));
    uint32_t b_cbit = (uint32_t)((lid >> 3) & 1);
    uint32_t b_rl   = b_row & 7;
    uint32_t b_base0 = sb + OFF_B + b_row * 256u;
    uint32_t b_base1 = b_base0 + 16u * 256u;

    CP_WAIT(1);                 // first K-half landed; second still in flight
    __syncthreads();
    #pragma unroll
    for (int kc = 0; kc < 4; kc++)
        k_step(kc, d, a_base0, a_base1, a_cbit, a_rl, b_base0, b_base1, b_cbit, b_rl);

    CP_WAIT(0);                 // second K-half landed
    __syncthreads();
    #pragma unroll
    for (int kc = 4; kc < 8; kc++)
        k_step(kc, d, a_base0, a_base1, a_cbit, a_rl, b_base0, b_base1, b_cbit, b_rl);

    // =============== Wait for sigma (long done by now) ====================
    if (tid == 0) spin_until((volatile int*)&g_flag2);
    __syncthreads();
    float c = __ldcg(&g_c);

    if (tid < TILE)
        reinterpret_cast<float*>(smem + OFF_CI)[tid] =
            -__ldcg(&g_norm[bi * TILE + tid]) * c;
    else if (tid < 2 * TILE)
        reinterpret_cast<float*>(smem + OFF_CJ)[tid - TILE] =
            -__ldcg(&g_norm[bj * TILE + (tid - TILE)]) * c;
    __syncthreads();

    // epilogue: out = ex2(dot * 2c + ci + cj)
    float sc2 = 2.f * c;
    const float* cis = reinterpret_cast<const float*>(smem + OFF_CI);
    const float* cjs = reinterpret_cast<const float*>(smem + OFF_CJ);
    int quad = lid >> 2;
    int qt   = lid & 3;

    #pragma unroll
    for (int mt = 0; mt < 2; mt++) {
        #pragma unroll
        for (int half = 0; half < 2; half++) {
            int r  = wm + mt * 16 + quad + half * 8;
            float ci = cis[r];
            float* orow = out + (size_t)(bi * TILE + r) * NROWS + (size_t)bj * TILE + wn2;
            #pragma unroll
            for (int nt = 0; nt < 4; nt++) {
                int col = nt * 8 + qt * 2;
                float e0 = fmaf(d[mt][nt][half * 2 + 0], sc2, ci + cjs[wn2 + col]);
                float e1 = fmaf(d[mt][nt][half * 2 + 1], sc2, ci + cjs[wn2 + col + 1]);
                *reinterpret_cast<float2*>(orow + col) = make_float2(ex2f(e0), ex2f(e1));
            }
        }
    }

    // =============== reset counters for next graph replay ===============
    __syncthreads();
    if (tid == 0) {
        if (atomicAdd(&g_ctr2, 1) == GRID - 1) {   // last CTA to exit
            g_ctr   = 0;
            g_ctr3  = 0;
            g_ctr2  = 0;
            g_flag1 = 0;
            g_flag2 = 0;
            #pragma unroll
            for (int g = 0; g < 16; g++) { g_gc[g] = 0; g_gflag[g] = 0; }
        }
    }
}

// ---------------------------------------------------------------------------
// Launch
// ---------------------------------------------------------------------------
extern "C" void kernel_launch(void* const* d_in, const int* in_sizes, int n_in,
                              void* d_out, int out_size) {
    const float* X = (const float*)d_in[0];
    float* out = (float*)d_out;
    (void)in_sizes; (void)n_in; (void)out_size;

    cudaFuncSetAttribute(gauss_fused_kernel,
                         cudaFuncAttributeMaxDynamicSharedMemorySize, SMEM_TOTAL);

    gauss_fused_kernel<<<GRID, NTHREADS, SMEM_TOTAL>>>(X, out);
}

// round 13
// speedup vs baseline: 1.2284x; 1.1379x over previous
#include <cuda_runtime.h>
#include <cuda_bf16.h>
#include <cstdint>

// ---------------------------------------------------------------------------
// Problem constants
// ---------------------------------------------------------------------------
#define NROWS 2048
#define NFEAT 128
#define TILE  128
#define PREP_BLOCKS 256           // 8 rows per block: shortest serial chain

// ---------------------------------------------------------------------------
// Device scratch (zero-initialized; no allocation allowed)
// ---------------------------------------------------------------------------
__device__ __nv_bfloat16 g_Xb[NROWS * NFEAT];        // bf16-quantized X
__device__ float g_norm[NROWS];                      // row norms of quantized X
__device__ float g_s_part[PREP_BLOCKS][NFEAT];       // per-block feature sums
__device__ float g_sumn_part[PREP_BLOCKS];           // per-block norm sums
__device__ float g_s2[8][NFEAT];                     // level-2 feature sums
__device__ float g_sn2[8];                           // level-2 norm sums
__device__ float g_c;                                // inv2s * log2(e)
__device__ int   g_ctr3;                             // sigma level-2 counter
__device__ int   g_ctr2;                             // exit counter
__device__ int   g_flag2;                            // sigma ready

// ---------------------------------------------------------------------------
// Helpers
// ---------------------------------------------------------------------------
__device__ __forceinline__ uint32_t smem_to_u32(const void* p) {
    uint32_t a;
    asm("{ .reg .u64 t; cvta.to.shared.u64 t, %1; cvt.u32.u64 %0, t; }" : "=r"(a) : "l"(p));
    return a;
}

__device__ __forceinline__ void ldmatrix_x4(uint32_t& r0, uint32_t& r1,
                                            uint32_t& r2, uint32_t& r3, uint32_t addr) {
    asm volatile("ldmatrix.sync.aligned.m8n8.x4.shared.b16 {%0,%1,%2,%3}, [%4];"
                 : "=r"(r0), "=r"(r1), "=r"(r2), "=r"(r3) : "r"(addr));
}

__device__ __forceinline__ void mma_16816(float* d, const uint32_t* a, const uint32_t* b) {
    asm volatile(
        "mma.sync.aligned.m16n8k16.row.col.f32.bf16.bf16.f32 "
        "{%0,%1,%2,%3}, {%4,%5,%6,%7}, {%8,%9}, {%0,%1,%2,%3};"
        : "+f"(d[0]), "+f"(d[1]), "+f"(d[2]), "+f"(d[3])
        : "r"(a[0]), "r"(a[1]), "r"(a[2]), "r"(a[3]), "r"(b[0]), "r"(b[1]));
}

__device__ __forceinline__ float ex2f(float x) {
    float r;
    asm("ex2.approx.ftz.f32 %0, %1;" : "=f"(r) : "f"(x));
    return r;
}

__device__ __forceinline__ void spin_until(volatile int* fp) {
    while (*fp == 0) { __nanosleep(32); }
}

// ---------------------------------------------------------------------------
// Kernel 1: prep. grid 256, block 256; block handles 8 rows (warp w = row w).
// Quantize -> g_Xb, row norms, per-block partials. NO finalize tail.
// ---------------------------------------------------------------------------
__global__ void __launch_bounds__(256) prep_kernel(const float* __restrict__ X) {
    int b   = blockIdx.x;
    int tid = threadIdx.x;
    int wid = tid >> 5;
    int lid = tid & 31;

    __shared__ float ss[8][NFEAT];
    __shared__ float sn[8];

    {
        int row = b * 8 + wid;
        float4 v = reinterpret_cast<const float4*>(X + (size_t)row * NFEAT)[lid];
        __nv_bfloat16 b0 = __float2bfloat16(v.x);
        __nv_bfloat16 b1 = __float2bfloat16(v.y);
        __nv_bfloat16 b2 = __float2bfloat16(v.z);
        __nv_bfloat16 b3 = __float2bfloat16(v.w);
        __nv_bfloat162* dst =
            reinterpret_cast<__nv_bfloat162*>(g_Xb + (size_t)row * NFEAT) + lid * 2;
        dst[0] = __nv_bfloat162(b0, b1);
        dst[1] = __nv_bfloat162(b2, b3);
        // quantized values downstream (diag exactly 0 -> out = 1)
        float fx = __bfloat162float(b0), fy = __bfloat162float(b1);
        float fz = __bfloat162float(b2), fw = __bfloat162float(b3);
        float sq = fx * fx + fy * fy + fz * fz + fw * fw;
        #pragma unroll
        for (int o = 16; o > 0; o >>= 1) sq += __shfl_xor_sync(0xFFFFFFFFu, sq, o);
        if (lid == 0) { g_norm[row] = sq; sn[wid] = sq; }
        ss[wid][lid * 4 + 0] = fx;
        ss[wid][lid * 4 + 1] = fy;
        ss[wid][lid * 4 + 2] = fz;
        ss[wid][lid * 4 + 3] = fw;
    }
    __syncthreads();
    if (tid < NFEAT) {
        float t = 0.f;
        #pragma unroll
        for (int w = 0; w < 8; w++) t += ss[w][tid];
        g_s_part[b][tid] = t;
    }
    if (tid == 0) {
        float t = 0.f;
        #pragma unroll
        for (int w = 0; w < 8; w++) t += sn[w];
        g_sumn_part[b] = t;
    }
}

// ---------------------------------------------------------------------------
// Kernel 2: main. grid (16,16), 256 threads (R3's measured-10.2us GEMM).
// CTAs 0..7 additionally reduce sigma (concurrent with everyone's GEMM);
// flag2 gates only the epilogue. Kernel boundary makes prep data visible.
// ---------------------------------------------------------------------------
#define OFF_CI  0
#define OFF_CJ  512
#define OFF_A   1024
#define OFF_B   (1024 + 32768)
#define OFF_FS  (OFF_B + 32768)
#define SMEM_TOTAL (OFF_FS + 1024)      // 67584 B -> 2 CTAs/SM

__global__ void __launch_bounds__(256, 2) gauss_main_kernel(float* __restrict__ out) {
    extern __shared__ char smem[];
    uint32_t sb = smem_to_u32(smem);
    int tid = threadIdx.x;
    int wid = tid >> 5;
    int lid = tid & 31;
    int bj  = blockIdx.x;
    int bi  = blockIdx.y;
    int b   = bi * 16 + bj;

    __shared__ float red[5];
    __shared__ int   s_last3;

    // =============== Sigma reduction on CTAs 0..7 (before their GEMM) ======
    if (b < 8) {
        float* ss2 = reinterpret_cast<float*>(smem + OFF_FS);  // [2][128]
        {
            int f = tid & 127;
            int g = tid >> 7;                 // 0 or 1; 16 partials each
            float sf = 0.f;
            #pragma unroll 16
            for (int p = b * 32 + g * 16; p < b * 32 + g * 16 + 16; p++)
                sf += g_s_part[p][f];
            ss2[g * NFEAT + f] = sf;
        }
        if (tid < 32) {
            float sna = g_sumn_part[b * 32 + tid];
            #pragma unroll
            for (int o = 16; o > 0; o >>= 1) sna += __shfl_xor_sync(0xFFFFFFFFu, sna, o);
            if (tid == 0) g_sn2[b] = sna;
        }
        __syncthreads();
        if (tid < NFEAT)
            g_s2[b][tid] = ss2[tid] + ss2[NFEAT + tid];
        __threadfence();
        __syncthreads();
        if (tid == 0) s_last3 = (atomicAdd(&g_ctr3, 1) == 7) ? 1 : 0;
        __syncthreads();
        if (s_last3) {
            if (tid < NFEAT) {
                float s = 0.f;
                #pragma unroll
                for (int q = 0; q < 8; q++) s += __ldcg(&g_s2[q][tid]);
                float v = s * s;
                #pragma unroll
                for (int o = 16; o > 0; o >>= 1) v += __shfl_xor_sync(0xFFFFFFFFu, v, o);
                if (lid == 0) red[wid] = v;
            }
            if (tid >= 224) {    // warp 7 sums sn2
                float sna = (lid < 8) ? __ldcg(&g_sn2[lid]) : 0.f;
                #pragma unroll
                for (int o = 4; o > 0; o >>= 1) sna += __shfl_xor_sync(0xFFFFFFFFu, sna, o);
                if (lid == 0) red[4] = sna;
            }
            __syncthreads();
            if (tid == 0) {
                float S2   = red[0] + red[1] + red[2] + red[3];
                float sumn = red[4];
                float Nf = (float)NROWS;
                float inv2s = (Nf * Nf) / (4.f * Nf * sumn - 4.f * S2);
                g_c = inv2s * 1.4426950408889634f;   // fold log2(e) for ex2
                __threadfence();
                *((volatile int*)&g_flag2) = 1;
            }
        }
    }

    // =============== Tile loads from g_Xb (prep data; kernel boundary) =====
    const uint4* A4 = reinterpret_cast<const uint4*>(g_Xb + (size_t)bi * TILE * NFEAT);
    const uint4* B4 = reinterpret_cast<const uint4*>(g_Xb + (size_t)bj * TILE * NFEAT);
    #pragma unroll
    for (int idx = tid; idx < 2048; idx += 256) {
        int row = idx >> 4;
        int ch  = idx & 15;
        uint32_t off = (uint32_t)row * 256u + (uint32_t)(ch ^ (row & 7)) * 16u;
        *reinterpret_cast<uint4*>(smem + OFF_A + off) = A4[idx];
        *reinterpret_cast<uint4*>(smem + OFF_B + off) = B4[idx];
    }
    __syncthreads();

    // =============== per-warp MMA: 4x2 warps, 32x64 each (R3 geometry) =====
    int wm = (wid & 3) * 32;
    int wn = (wid >> 2) * 64;

    float d[2][8][4];
    #pragma unroll
    for (int mt = 0; mt < 2; mt++)
        #pragma unroll
        for (int nt = 0; nt < 8; nt++)
            #pragma unroll
            for (int e = 0; e < 4; e++) d[mt][nt][e] = 0.f;

    uint32_t a_row  = (uint32_t)(wm + (lid & 15));
    uint32_t a_cbit = (uint32_t)(lid >> 4);
    uint32_t a_rl   = a_row & 7;
    uint32_t a_base0 = sb + OFF_A + a_row * 256u;
    uint32_t a_base1 = a_base0 + 16u * 256u;

    uint32_t b_row  = (uint32_t)(wn + (lid & 7) + ((lid & 16) >> 1));
    uint32_t b_cbit = (uint32_t)((lid >> 3) & 1);
    uint32_t b_rl   = b_row & 7;
    uint32_t b_base = sb + OFF_B + b_row * 256u;

    // double-buffered fragments: load kc+1 while issuing kc's MMAs
    uint32_t af[2][2][4];
    uint32_t bf[2][8][2];

#define LOAD_A(kc, bufi) do {                                                   \
        uint32_t sc = ((uint32_t)(2 * (kc)) + a_cbit) ^ a_rl;                   \
        ldmatrix_x4(af[bufi][0][0], af[bufi][0][1], af[bufi][0][2],             \
                    af[bufi][0][3], a_base0 + (sc << 4));                       \
        ldmatrix_x4(af[bufi][1][0], af[bufi][1][1], af[bufi][1][2],             \
                    af[bufi][1][3], a_base1 + (sc << 4));                       \
    } while (0)

#define LOAD_B(kc, bufi) do {                                                   \
        uint32_t sc = ((uint32_t)(2 * (kc)) + b_cbit) ^ b_rl;                   \
        _Pragma("unroll")                                                       \
        for (int p = 0; p < 4; p++) {                                           \
            uint32_t addr = b_base + (uint32_t)p * (16u * 256u) + (sc << 4);    \
            ldmatrix_x4(bf[bufi][2 * p][0], bf[bufi][2 * p][1],                 \
                        bf[bufi][2 * p + 1][0], bf[bufi][2 * p + 1][1], addr);  \
        }                                                                       \
    } while (0)

    LOAD_A(0, 0);
    LOAD_B(0, 0);
    #pragma unroll
    for (int kc = 0; kc < 8; kc++) {
        int cur = kc & 1, nxt = cur ^ 1;
        if (kc < 7) { LOAD_A(kc + 1, nxt); LOAD_B(kc + 1, nxt); }
        #pragma unroll
        for (int mt = 0; mt < 2; mt++)
            #pragma unroll
            for (int nt = 0; nt < 8; nt++)
                mma_16816(d[mt][nt], af[cur][mt], bf[cur][nt]);
    }
#undef LOAD_A
#undef LOAD_B

    // =============== Wait for sigma (long done for most CTAs) =============
    if (tid == 0) spin_until((volatile int*)&g_flag2);
    __syncthreads();
    float c = __ldcg(&g_c);

    // const tiles: ci = -ni*c, cj = -nj*c (g_norm from prep launch)
    if (tid < TILE)
        reinterpret_cast<float*>(smem + OFF_CI)[tid] = -g_norm[bi * TILE + tid] * c;
    else
        reinterpret_cast<float*>(smem + OFF_CJ)[tid - TILE] =
            -g_norm[bj * TILE + (tid - TILE)] * c;
    __syncthreads();

    // epilogue: out = ex2(dot * 2c + ci + cj)
    float sc2 = 2.f * c;
    const float* cis = reinterpret_cast<const float*>(smem + OFF_CI);
    const float* cjs = reinterpret_cast<const float*>(smem + OFF_CJ);
    int quad = lid >> 2;
    int qt   = lid & 3;

    #pragma unroll
    for (int mt = 0; mt < 2; mt++) {
        #pragma unroll
        for (int half = 0; half < 2; half++) {
            int r  = wm + mt * 16 + quad + half * 8;
            float ci = cis[r];
            float* orow = out + (size_t)(bi * TILE + r) * NROWS + (size_t)bj * TILE + wn;
            #pragma unroll
            for (int nt = 0; nt < 8; nt++) {
                int col = nt * 8 + qt * 2;
                float e0 = fmaf(d[mt][nt][half * 2 + 0], sc2, ci + cjs[wn + col]);
                float e1 = fmaf(d[mt][nt][half * 2 + 1], sc2, ci + cjs[wn + col + 1]);
                *reinterpret_cast<float2*>(orow + col) = make_float2(ex2f(e0), ex2f(e1));
            }
        }
    }

    // =============== reset counters for next graph replay ================
    __syncthreads();
    if (tid == 0) {
        if (atomicAdd(&g_ctr2, 1) == 255) {   // last CTA to exit
            g_ctr3  = 0;
            g_ctr2  = 0;
            g_flag2 = 0;
        }
    }
}

// ---------------------------------------------------------------------------
// Launch
// ---------------------------------------------------------------------------
extern "C" void kernel_launch(void* const* d_in, const int* in_sizes, int n_in,
                              void* d_out, int out_size) {
    const float* X = (const float*)d_in[0];
    float* out = (float*)d_out;
    (void)in_sizes; (void)n_in; (void)out_size;

    cudaFuncSetAttribute(gauss_main_kernel,
                         cudaFuncAttributeMaxDynamicSharedMemorySize, SMEM_TOTAL);

    prep_kernel<<<PREP_BLOCKS, 256>>>(X);
    gauss_main_kernel<<<dim3(16, 16), 256, SMEM_TOTAL>>>(out);
}

// round 14
// speedup vs baseline: 1.2311x; 1.0022x over previous
#include <cuda_runtime.h>
#include <cuda_bf16.h>
#include <cstdint>

// ---------------------------------------------------------------------------
// Problem constants
// ---------------------------------------------------------------------------
#define NROWS 2048
#define NFEAT 128
#define TILE  128
#define PREP_BLOCKS 256           // 8 rows per block: shortest serial chain
#define MAIN_CTAS 264             // 256 tile CTAs + 8 sigma-reducer CTAs
#define NTHREADS 512

// ---------------------------------------------------------------------------
// Device scratch (zero-initialized; no allocation allowed)
// ---------------------------------------------------------------------------
__device__ __nv_bfloat16 g_Xb[NROWS * NFEAT];        // bf16-quantized X
__device__ float g_norm[NROWS];                      // row norms of quantized X
__device__ float g_s_part[PREP_BLOCKS][NFEAT];       // per-block feature sums
__device__ float g_sumn_part[PREP_BLOCKS];           // per-block norm sums
__device__ float g_s2[8][NFEAT];                     // level-2 feature sums
__device__ float g_sn2[8];                           // level-2 norm sums
__device__ float g_c;                                // inv2s * log2(e)
__device__ int   g_ctr3;                             // sigma level-2 counter
__device__ int   g_ctr2;                             // exit counter
__device__ int   g_flag2;                            // sigma ready

// ---------------------------------------------------------------------------
// Helpers
// ---------------------------------------------------------------------------
__device__ __forceinline__ uint32_t smem_to_u32(const void* p) {
    uint32_t a;
    asm("{ .reg .u64 t; cvta.to.shared.u64 t, %1; cvt.u32.u64 %0, t; }" : "=r"(a) : "l"(p));
    return a;
}

__device__ __forceinline__ void ldmatrix_x4(uint32_t& r0, uint32_t& r1,
                                            uint32_t& r2, uint32_t& r3, uint32_t addr) {
    asm volatile("ldmatrix.sync.aligned.m8n8.x4.shared.b16 {%0,%1,%2,%3}, [%4];"
                 : "=r"(r0), "=r"(r1), "=r"(r2), "=r"(r3) : "r"(addr));
}

__device__ __forceinline__ void mma_16816(float* d, const uint32_t* a, const uint32_t* b) {
    asm volatile(
        "mma.sync.aligned.m16n8k16.row.col.f32.bf16.bf16.f32 "
        "{%0,%1,%2,%3}, {%4,%5,%6,%7}, {%8,%9}, {%0,%1,%2,%3};"
        : "+f"(d[0]), "+f"(d[1]), "+f"(d[2]), "+f"(d[3])
        : "r"(a[0]), "r"(a[1]), "r"(a[2]), "r"(a[3]), "r"(b[0]), "r"(b[1]));
}

__device__ __forceinline__ float ex2f(float x) {
    float r;
    asm("ex2.approx.ftz.f32 %0, %1;" : "=f"(r) : "f"(x));
    return r;
}

__device__ __forceinline__ void spin_until(volatile int* fp) {
    while (*fp == 0) { __nanosleep(32); }
}

// ---------------------------------------------------------------------------
// Kernel 1: prep. grid 256, block 256; block handles 8 rows (warp w = row w).
// ---------------------------------------------------------------------------
__global__ void __launch_bounds__(256) prep_kernel(const float* __restrict__ X) {
    int b   = blockIdx.x;
    int tid = threadIdx.x;
    int wid = tid >> 5;
    int lid = tid & 31;

    __shared__ float ss[8][NFEAT];
    __shared__ float sn[8];

    {
        int row = b * 8 + wid;
        float4 v = reinterpret_cast<const float4*>(X + (size_t)row * NFEAT)[lid];
        __nv_bfloat16 b0 = __float2bfloat16(v.x);
        __nv_bfloat16 b1 = __float2bfloat16(v.y);
        __nv_bfloat16 b2 = __float2bfloat16(v.z);
        __nv_bfloat16 b3 = __float2bfloat16(v.w);
        __nv_bfloat162* dst =
            reinterpret_cast<__nv_bfloat162*>(g_Xb + (size_t)row * NFEAT) + lid * 2;
        dst[0] = __nv_bfloat162(b0, b1);
        dst[1] = __nv_bfloat162(b2, b3);
        // quantized values downstream (diag exactly 0 -> out = 1)
        float fx = __bfloat162float(b0), fy = __bfloat162float(b1);
        float fz = __bfloat162float(b2), fw = __bfloat162float(b3);
        float sq = fx * fx + fy * fy + fz * fz + fw * fw;
        #pragma unroll
        for (int o = 16; o > 0; o >>= 1) sq += __shfl_xor_sync(0xFFFFFFFFu, sq, o);
        if (lid == 0) { g_norm[row] = sq; sn[wid] = sq; }
        ss[wid][lid * 4 + 0] = fx;
        ss[wid][lid * 4 + 1] = fy;
        ss[wid][lid * 4 + 2] = fz;
        ss[wid][lid * 4 + 3] = fw;
    }
    __syncthreads();
    if (tid < NFEAT) {
        float t = 0.f;
        #pragma unroll
        for (int w = 0; w < 8; w++) t += ss[w][tid];
        g_s_part[b][tid] = t;
    }
    if (tid == 0) {
        float t = 0.f;
        #pragma unroll
        for (int w = 0; w < 8; w++) t += sn[w];
        g_sumn_part[b] = t;
    }
}

// ---------------------------------------------------------------------------
// Kernel 2: main. grid 264 x 512 threads.
//   b <  256 : GEMM tile CTA (bi = b>>4, bj = b&15), 4x4 warp grid of 32x32.
//   b >= 256 : sigma reducer CTA (8 of them); reduce -> flag2 -> exit.
// flag2 gates only the epilogue (free by then for tile CTAs).
// ---------------------------------------------------------------------------
#define OFF_CI  0
#define OFF_CJ  512
#define OFF_A   1024
#define OFF_B   (1024 + 32768)
#define OFF_FS  (OFF_B + 32768)
#define SMEM_TOTAL (OFF_FS + 2048)      // 68608 B -> 2 CTAs/SM

__global__ void __launch_bounds__(NTHREADS, 2) gauss_main_kernel(float* __restrict__ out) {
    extern __shared__ char smem[];
    uint32_t sb = smem_to_u32(smem);
    int b   = blockIdx.x;
    int tid = threadIdx.x;
    int wid = tid >> 5;
    int lid = tid & 31;

    __shared__ float red[5];
    __shared__ int   s_last3;

    // =============== Sigma reducer CTAs (b >= 256): reduce and exit ========
    if (b >= 256) {
        int b2 = b - 256;                                      // 0..7
        float* ss2 = reinterpret_cast<float*>(smem + OFF_FS);  // [4][128]
        {
            int f = tid & 127;
            int g = tid >> 7;                                  // 0..3
            float sf = 0.f;
            #pragma unroll
            for (int p = b2 * 32 + g * 8; p < b2 * 32 + g * 8 + 8; p++)
                sf += g_s_part[p][f];
            ss2[g * NFEAT + f] = sf;
        }
        if (tid < 32) {
            float sna = g_sumn_part[b2 * 32 + tid];
            #pragma unroll
            for (int o = 16; o > 0; o >>= 1) sna += __shfl_xor_sync(0xFFFFFFFFu, sna, o);
            if (tid == 0) g_sn2[b2] = sna;
        }
        __syncthreads();
        if (tid < NFEAT)
            g_s2[b2][tid] = ss2[tid] + ss2[NFEAT + tid] +
                            ss2[2 * NFEAT + tid] + ss2[3 * NFEAT + tid];
        __threadfence();
        __syncthreads();
        if (tid == 0) s_last3 = (atomicAdd(&g_ctr3, 1) == 7) ? 1 : 0;
        __syncthreads();
        if (s_last3) {
            if (tid < NFEAT) {
                float s = 0.f;
                #pragma unroll
                for (int q = 0; q < 8; q++) s += __ldcg(&g_s2[q][tid]);
                float v = s * s;
                #pragma unroll
                for (int o = 16; o > 0; o >>= 1) v += __shfl_xor_sync(0xFFFFFFFFu, v, o);
                if (lid == 0) red[wid] = v;
            }
            if (tid >= 480) {          // spare warp sums sn2
                float sna = (lid < 8) ? __ldcg(&g_sn2[lid]) : 0.f;
                #pragma unroll
                for (int o = 4; o > 0; o >>= 1) sna += __shfl_xor_sync(0xFFFFFFFFu, sna, o);
                if (lid == 0) red[4] = sna;
            }
            __syncthreads();
            if (tid == 0) {
                float S2   = red[0] + red[1] + red[2] + red[3];
                float sumn = red[4];
                float Nf = (float)NROWS;
                float inv2s = (Nf * Nf) / (4.f * Nf * sumn - 4.f * S2);
                g_c = inv2s * 1.4426950408889634f;   // fold log2(e) for ex2
                __threadfence();
                *((volatile int*)&g_flag2) = 1;
            }
        }
        // exit bookkeeping
        if (tid == 0) {
            if (atomicAdd(&g_ctr2, 1) == MAIN_CTAS - 1) {
                g_ctr3 = 0; g_ctr2 = 0; g_flag2 = 0;
            }
        }
        return;
    }

    // =============== GEMM tile CTA ==========================================
    int bj = b & 15;
    int bi = b >> 4;

    const uint4* A4 = reinterpret_cast<const uint4*>(g_Xb + (size_t)bi * TILE * NFEAT);
    const uint4* B4 = reinterpret_cast<const uint4*>(g_Xb + (size_t)bj * TILE * NFEAT);
    #pragma unroll
    for (int idx = tid; idx < 2048; idx += NTHREADS) {
        int row = idx >> 4;
        int ch  = idx & 15;
        uint32_t off = (uint32_t)row * 256u + (uint32_t)(ch ^ (row & 7)) * 16u;
        *reinterpret_cast<uint4*>(smem + OFF_A + off) = A4[idx];
        *reinterpret_cast<uint4*>(smem + OFF_B + off) = B4[idx];
    }
    __syncthreads();

    // per-warp MMA: 16 warps as 4x4 grid of 32x32 subtiles
    int wm  = (wid & 3) * 32;
    int wn2 = (wid >> 2) * 32;

    float d[2][4][4];
    #pragma unroll
    for (int mt = 0; mt < 2; mt++)
        #pragma unroll
        for (int nt = 0; nt < 4; nt++)
            #pragma unroll
            for (int e = 0; e < 4; e++) d[mt][nt][e] = 0.f;

    uint32_t a_row  = (uint32_t)(wm + (lid & 15));
    uint32_t a_cbit = (uint32_t)(lid >> 4);
    uint32_t a_rl   = a_row & 7;
    uint32_t a_base0 = sb + OFF_A + a_row * 256u;
    uint32_t a_base1 = a_base0 + 16u * 256u;

    uint32_t b_row  = (uint32_t)(wn2 + (lid & 7) + ((lid & 16) >> 1));
    uint32_t b_cbit = (uint32_t)((lid >> 3) & 1);
    uint32_t b_rl   = b_row & 7;
    uint32_t b_base0 = sb + OFF_B + b_row * 256u;
    uint32_t b_base1 = b_base0 + 16u * 256u;

    #pragma unroll
    for (int kc = 0; kc < 8; kc++) {
        uint32_t af[2][4];
        uint32_t bfr[4][2];
        uint32_t sca = ((uint32_t)(2 * kc) + a_cbit) ^ a_rl;
        ldmatrix_x4(af[0][0], af[0][1], af[0][2], af[0][3], a_base0 + (sca << 4));
        ldmatrix_x4(af[1][0], af[1][1], af[1][2], af[1][3], a_base1 + (sca << 4));
        uint32_t scb = ((uint32_t)(2 * kc) + b_cbit) ^ b_rl;
        ldmatrix_x4(bfr[0][0], bfr[0][1], bfr[1][0], bfr[1][1], b_base0 + (scb << 4));
        ldmatrix_x4(bfr[2][0], bfr[2][1], bfr[3][0], bfr[3][1], b_base1 + (scb << 4));
        #pragma unroll
        for (int mt = 0; mt < 2; mt++)
            #pragma unroll
            for (int nt = 0; nt < 4; nt++)
                mma_16816(d[mt][nt], af[mt], bfr[nt]);
    }

    // =============== Wait for sigma (long done by now) =====================
    if (tid == 0) spin_until((volatile int*)&g_flag2);
    __syncthreads();
    float c = __ldcg(&g_c);

    if (tid < TILE)
        reinterpret_cast<float*>(smem + OFF_CI)[tid] = -g_norm[bi * TILE + tid] * c;
    else if (tid < 2 * TILE)
        reinterpret_cast<float*>(smem + OFF_CJ)[tid - TILE] =
            -g_norm[bj * TILE + (tid - TILE)] * c;
    __syncthreads();

    // epilogue: out = ex2(dot * 2c + ci + cj)
    float sc2 = 2.f * c;
    const float* cis = reinterpret_cast<const float*>(smem + OFF_CI);
    const float* cjs = reinterpret_cast<const float*>(smem + OFF_CJ);
    int quad = lid >> 2;
    int qt   = lid & 3;

    #pragma unroll
    for (int mt = 0; mt < 2; mt++) {
        #pragma unroll
        for (int half = 0; half < 2; half++) {
            int r  = wm + mt * 16 + quad + half * 8;
            float ci = cis[r];
            float* orow = out + (size_t)(bi * TILE + r) * NROWS + (size_t)bj * TILE + wn2;
            #pragma unroll
            for (int nt = 0; nt < 4; nt++) {
                int col = nt * 8 + qt * 2;
                float e0 = fmaf(d[mt][nt][half * 2 + 0], sc2, ci + cjs[wn2 + col]);
                float e1 = fmaf(d[mt][nt][half * 2 + 1], sc2, ci + cjs[wn2 + col + 1]);
                *reinterpret_cast<float2*>(orow + col) = make_float2(ex2f(e0), ex2f(e1));
            }
        }
    }

    // =============== reset counters for next graph replay ==================
    __syncthreads();
    if (tid == 0) {
        if (atomicAdd(&g_ctr2, 1) == MAIN_CTAS - 1) {
            g_ctr3 = 0; g_ctr2 = 0; g_flag2 = 0;
        }
    }
}

// ---------------------------------------------------------------------------
// Launch
// ---------------------------------------------------------------------------
extern "C" void kernel_launch(void* const* d_in, const int* in_sizes, int n_in,
                              void* d_out, int out_size) {
    const float* X = (const float*)d_in[0];
    float* out = (float*)d_out;
    (void)in_sizes; (void)n_in; (void)out_size;

    cudaFuncSetAttribute(gauss_main_kernel,
                         cudaFuncAttributeMaxDynamicSharedMemorySize, SMEM_TOTAL);

    prep_kernel<<<PREP_BLOCKS, 256>>>(X);
    gauss_main_kernel<<<MAIN_CTAS, NTHREADS, SMEM_TOTAL>>>(out);
}